// round 3
// baseline (speedup 1.0000x reference)
#include <cuda_runtime.h>
#include <cuda_bf16.h>
#include <cstdint>

// Problem constants (fixed by the dataset)
#define MAX_NODES 100000
#define D_FEAT    128

// Per-node precomputed partial logits.
// A[n] = (emb[n] . W[0, 0:128] + b0 , emb[n] . W[1, 0:128] + b1)   -- source-side
// B[n] = (emb[n] . W[0,128:256]     , emb[n] . W[1,128:256])       -- dest-side
__device__ float2 g_A[MAX_NODES];
__device__ float2 g_B[MAX_NODES];

// 1 if edge_index buffer holds int64 elements, 0 if int32.
__device__ int g_idx_is64;

// ---------------------------------------------------------------------------
// Detect index dtype on device (graph-capture safe; deterministic).
// For little-endian int64 values in [0, 100000), every odd 32-bit word is 0.
// For int32 data those words are random node ids (all-zero prob ~ 1e-160).
// ---------------------------------------------------------------------------
__global__ void detect_idx_kernel(const unsigned int* __restrict__ idx_words,
                                  int n_words_to_check)
{
    unsigned int acc = 0;
    for (int i = 1; i < n_words_to_check; i += 2) acc |= idx_words[i];
    g_idx_is64 = (acc == 0u) ? 1 : 0;
}

// ---------------------------------------------------------------------------
// Kernel 1: warp-per-node partial logit computation.
// Each warp streams one node's 128 floats (4 coalesced 128B transactions)
// and computes 4 dot products against W staged in shared memory.
// ---------------------------------------------------------------------------
__global__ __launch_bounds__(256)
void node_scores_kernel(const float* __restrict__ emb,
                        const float* __restrict__ W,
                        const float* __restrict__ bias,
                        int n_nodes)
{
    __shared__ float Ws[512];  // W is [2, 256] row-major = 512 floats
    for (int i = threadIdx.x; i < 512; i += blockDim.x) Ws[i] = W[i];
    __syncthreads();

    const int warp = (int)((blockIdx.x * (unsigned)blockDim.x + threadIdx.x) >> 5);
    const int lane = threadIdx.x & 31;
    if (warp >= n_nodes) return;

    const float* __restrict__ x = emb + (size_t)warp * D_FEAT;

    float a0 = 0.f, b0 = 0.f, a1 = 0.f, b1 = 0.f;
#pragma unroll
    for (int i = 0; i < 4; i++) {
        const int k = lane + i * 32;
        const float v = __ldg(&x[k]);
        a0 = fmaf(v, Ws[k],        a0);   // out0, source half
        b0 = fmaf(v, Ws[128 + k],  b0);   // out0, dest half
        a1 = fmaf(v, Ws[256 + k],  a1);   // out1, source half
        b1 = fmaf(v, Ws[384 + k],  b1);   // out1, dest half
    }

#pragma unroll
    for (int off = 16; off; off >>= 1) {
        a0 += __shfl_xor_sync(0xFFFFFFFFu, a0, off);
        b0 += __shfl_xor_sync(0xFFFFFFFFu, b0, off);
        a1 += __shfl_xor_sync(0xFFFFFFFFu, a1, off);
        b1 += __shfl_xor_sync(0xFFFFFFFFu, b1, off);
    }

    if (lane == 0) {
        g_A[warp] = make_float2(a0 + bias[0], a1 + bias[1]);
        g_B[warp] = make_float2(b0, b1);
    }
}

// ---------------------------------------------------------------------------
// Kernel 2: per-edge gather from the L2-resident tables + 2-way softmax.
// Handles both int32 and int64 edge_index via the device-side flag
// (uniform branch — negligible cost).
// ---------------------------------------------------------------------------
__global__ __launch_bounds__(256)
void edge_softmax_kernel(const void* __restrict__ ei_raw,
                         float2* __restrict__ out,
                         int n_edges)
{
    const int e = (int)(blockIdx.x * (unsigned)blockDim.x + threadIdx.x);
    if (e >= n_edges) return;

    int r, c;
    if (g_idx_is64) {
        const long long* ei = (const long long*)ei_raw;
        r = (int)__ldg(&ei[e]);
        c = (int)__ldg(&ei[n_edges + e]);
    } else {
        const int* ei = (const int*)ei_raw;
        r = __ldg(&ei[e]);
        c = __ldg(&ei[n_edges + e]);
    }

    // Safety clamp: never fault even on unexpected data.
    r = min(max(r, 0), MAX_NODES - 1);
    c = min(max(c, 0), MAX_NODES - 1);

    const float2 A = g_A[r];
    const float2 B = g_B[c];

    const float s0 = A.x + B.x;
    const float s1 = A.y + B.y;

    // numerically stable 2-way softmax
    const float m   = fmaxf(s0, s1);
    const float e0  = __expf(s0 - m);
    const float e1  = __expf(s1 - m);
    const float inv = 1.0f / (e0 + e1);

    out[e] = make_float2(e0 * inv, e1 * inv);
}

// ---------------------------------------------------------------------------
extern "C" void kernel_launch(void* const* d_in, const int* in_sizes, int n_in,
                              void* d_out, int out_size)
{
    // Bind inputs by element count (all four are distinct):
    //   node_embeddings: N*128 (largest), edge_index: 2*E, W: 512, b: 2
    const float* emb  = nullptr; int emb_elems = 0;
    const void*  ei   = nullptr; int ei_elems  = 0;
    const float* W    = nullptr;
    const float* bias = nullptr;

    // Find the two large buffers: largest = embeddings, second = edge_index.
    int i_emb = -1, i_ei = -1;
    for (int i = 0; i < n_in; i++) {
        if (i_emb < 0 || in_sizes[i] > in_sizes[i_emb]) i_emb = i;
    }
    for (int i = 0; i < n_in; i++) {
        if (i == i_emb) continue;
        if (i_ei < 0 || in_sizes[i] > in_sizes[i_ei]) i_ei = i;
    }
    emb = (const float*)d_in[i_emb]; emb_elems = in_sizes[i_emb];
    ei  = d_in[i_ei];                ei_elems  = in_sizes[i_ei];
    for (int i = 0; i < n_in; i++) {
        if (i == i_emb || i == i_ei) continue;
        if (in_sizes[i] > 16) W = (const float*)d_in[i];    // 512 elems
        else                  bias = (const float*)d_in[i]; // 2 elems
    }
    // Positional fallback (should not trigger with the known 4-input layout).
    if (!W    && n_in > 2) W    = (const float*)d_in[2];
    if (!bias && n_in > 3) bias = (const float*)d_in[3];

    const int n_nodes = emb_elems / D_FEAT;
    const int n_edges = ei_elems / 2;
    float2* out = (float2*)d_out;  // [E, 2] float32

    // Kernel 0: detect whether edge_index is int32 or int64 (device-side).
    detect_idx_kernel<<<1, 1>>>((const unsigned int*)ei, 64);

    // Kernel 1: one warp per node, 8 warps per block
    {
        const int warps_per_block = 8;
        const int blocks = (n_nodes + warps_per_block - 1) / warps_per_block;
        node_scores_kernel<<<blocks, warps_per_block * 32>>>(emb, W, bias, n_nodes);
    }

    // Kernel 2: one thread per edge
    {
        const int threads = 256;
        const int blocks = (n_edges + threads - 1) / threads;
        edge_softmax_kernel<<<blocks, threads>>>(ei, out, n_edges);
    }
}